// round 17
// baseline (speedup 1.0000x reference)
#include <cuda_runtime.h>
#include <cstdint>

// ---------------------------------------------------------------------------
// Sparse CNN backbone, fp32, channel-QUAD SoA layout [C/4][n] float4.
// Convs: K-split WITHIN the CTA (warp-group 0 = taps [0,KH), group 1 =
// [KH,27), same rows), smem combine -> single z buffer; BN stats fused into
// the conv epilogue. 24 warps/SM, grids ~460 CTAs.
// ---------------------------------------------------------------------------

#define MAXN2 80000
#define MAXN4 13824
#define MAXT 256   // max 256-row tiles

__device__ float g_xc[MAXN2 * 32];
__device__ float g_z[MAXN2 * 32];
__device__ float g_xt[MAXN2 * 32];
__device__ float g_y[MAXN4 * 64];
__device__ float g_part[64 * MAXT * 2];

typedef unsigned long long ull;

__device__ __forceinline__ ull pack2(float x) {
    ull r;
    asm("mov.b64 %0, {%1, %1};" : "=l"(r) : "f"(x));
    return r;
}
__device__ __forceinline__ void fma2(ull& d, ull a, ull b) {
    asm("fma.rn.f32x2 %0, %1, %2, %0;" : "+l"(d) : "l"(a), "l"(b));
}

// ---------------------------------------------------------------------------
// In-CTA K-split conv, quad layout. 256 threads = 2 groups of 128.
// Group g handles taps [g? KH:0, g? 27:KH) for rows r0=bx*256+wtid, r1=r0+128.
// Epilogue: group1 dumps accs to smem, group0 combines, stores z once, and
// (STATS) computes per-(channel,tile) sum/sumsq partials.
// ---------------------------------------------------------------------------
template <int CIN, int SLICE, bool STATS>
__global__ __launch_bounds__(256, 3) void conv_m(
    const float4* __restrict__ fT4, const float* __restrict__ W,
    const int* __restrict__ in_map, int n_in, int n_out, int COUT, int KH,
    float4* __restrict__ oT4, float* __restrict__ part) {
    extern __shared__ float sW[];  // [27][CIN][SLICE] floats
    const int tid = threadIdx.x;
    const int wg = tid >> 7;
    const int wtid = tid & 127;
    const int yoff = blockIdx.y * SLICE;
    constexpr int WV = SLICE / 4;
    constexpr int QB = CIN / 8;

    for (int i = tid; i < 27 * CIN * WV; i += 256) {
        int r = i / WV, c4 = (i % WV) * 4;
        reinterpret_cast<float4*>(sW)[i] = *reinterpret_cast<const float4*>(
            W + (size_t)r * COUT + yoff + c4);
    }
    __syncthreads();

    const int r0 = blockIdx.x * 256 + wtid;
    const int r1 = r0 + 128;
    const bool ok0 = r0 < n_out, ok1 = r1 < n_out;
    const int k0 = wg ? KH : 0;
    const int k1 = wg ? 27 : KH;

    ull acc0[SLICE / 2], acc1[SLICE / 2];
#pragma unroll
    for (int i = 0; i < SLICE / 2; i++) { acc0[i] = 0ull; acc1[i] = 0ull; }

    int i0n = ok0 ? __ldg(&in_map[(size_t)k0 * n_out + r0]) : n_in;
    int i1n = ok1 ? __ldg(&in_map[(size_t)k0 * n_out + r1]) : n_in;
    const float4 z4 = make_float4(0.f, 0.f, 0.f, 0.f);

    for (int k = k0; k < k1; k++) {
        const int i0 = i0n, i1 = i1n;
        if (k + 1 < k1) {
            const int* mp = in_map + (size_t)(k + 1) * n_out;
            i0n = ok0 ? __ldg(&mp[r0]) : n_in;
            i1n = ok1 ? __ldg(&mp[r1]) : n_in;
        }
        const bool v0 = i0 < n_in, v1 = i1 < n_in;
        if (__ballot_sync(0xffffffffu, v0 | v1) == 0u) continue;

        const float* wk = sW + (size_t)k * CIN * SLICE;
#pragma unroll
        for (int q = 0; q < QB; q++) {
            float4 A0 = v0 ? __ldg(fT4 + (size_t)(2 * q) * n_in + i0) : z4;
            float4 B0 = v0 ? __ldg(fT4 + (size_t)(2 * q + 1) * n_in + i0) : z4;
            float4 A1 = v1 ? __ldg(fT4 + (size_t)(2 * q) * n_in + i1) : z4;
            float4 B1 = v1 ? __ldg(fT4 + (size_t)(2 * q + 1) * n_in + i1) : z4;
            float e0[4] = {A0.x, A0.z, B0.x, B0.z};
            float o0[4] = {A0.y, A0.w, B0.y, B0.w};
            float e1[4] = {A1.x, A1.z, B1.x, B1.z};
            float o1[4] = {A1.y, A1.w, B1.y, B1.w};
#pragma unroll
            for (int j = 0; j < 4; j++) {
                const int c0 = q * 8 + 2 * j;
                ull a00 = pack2(e0[j]), a01 = pack2(o0[j]);
                ull a10 = pack2(e1[j]), a11 = pack2(o1[j]);
                const ulonglong2* w0 =
                    reinterpret_cast<const ulonglong2*>(wk + c0 * SLICE);
                const ulonglong2* w1 =
                    reinterpret_cast<const ulonglong2*>(wk + (c0 + 1) * SLICE);
#pragma unroll
                for (int p = 0; p < SLICE / 4; p++) {
                    ulonglong2 wa = w0[p], wb = w1[p];
                    fma2(acc0[2 * p], a00, wa.x);
                    fma2(acc0[2 * p + 1], a00, wa.y);
                    fma2(acc1[2 * p], a10, wa.x);
                    fma2(acc1[2 * p + 1], a10, wa.y);
                    fma2(acc0[2 * p], a01, wb.x);
                    fma2(acc0[2 * p + 1], a01, wb.y);
                    fma2(acc1[2 * p], a11, wb.x);
                    fma2(acc1[2 * p + 1], a11, wb.y);
                }
            }
        }
    }

    float v0s[SLICE], v1s[SLICE];
#pragma unroll
    for (int p = 0; p < SLICE / 2; p++) {
        float2 a = *reinterpret_cast<float2*>(&acc0[p]);
        v0s[2 * p] = a.x; v0s[2 * p + 1] = a.y;
        float2 b = *reinterpret_cast<float2*>(&acc1[p]);
        v1s[2 * p] = b.x; v1s[2 * p + 1] = b.y;
    }

    // Combine group1 into group0 via smem (reuse weight area).
    __syncthreads();
    float* cmb = sW;  // 256*SLICE floats
    if (wg == 1) {
#pragma unroll
        for (int s = 0; s < SLICE; s++) {
            cmb[wtid * SLICE + s] = v0s[s];
            cmb[(wtid + 128) * SLICE + s] = v1s[s];
        }
    }
    __syncthreads();
    if (wg == 0) {
#pragma unroll
        for (int s = 0; s < SLICE; s++) {
            v0s[s] += cmb[wtid * SLICE + s];
            v1s[s] += cmb[(wtid + 128) * SLICE + s];
        }
        if (ok0) {
#pragma unroll
            for (int p = 0; p < WV; p++)
                oT4[(size_t)(yoff / 4 + p) * n_out + r0] = make_float4(
                    v0s[4 * p], v0s[4 * p + 1], v0s[4 * p + 2], v0s[4 * p + 3]);
        }
        if (ok1) {
#pragma unroll
            for (int p = 0; p < WV; p++)
                oT4[(size_t)(yoff / 4 + p) * n_out + r1] = make_float4(
                    v1s[4 * p], v1s[4 * p + 1], v1s[4 * p + 2], v1s[4 * p + 3]);
        }
    }

    if (STATS) {
        __syncthreads();
        float* sv = sW;                  // 128*SLICE
        float* sq = sW + 128 * SLICE;    // 128*SLICE
        if (wg == 0) {
#pragma unroll
            for (int s = 0; s < SLICE; s++) {
                // OOB rows carry exact-zero accumulators
                sv[wtid * SLICE + s] = v0s[s] + v1s[s];
                sq[wtid * SLICE + s] = v0s[s] * v0s[s] + v1s[s] * v1s[s];
            }
        }
        __syncthreads();
        constexpr int G = 128 / SLICE;
        const int c = wtid % SLICE, g = wtid / SLICE;
        float S = 0.f, Q = 0.f;
        if (wg == 0) {
            for (int r = g; r < 128; r += G) {
                S += sv[r * SLICE + c];
                Q += sq[r * SLICE + c];
            }
        }
        __syncthreads();
        if (wg == 0) {
            sv[g * SLICE + c] = S;
            sq[g * SLICE + c] = Q;
        }
        __syncthreads();
        if (tid < SLICE) {
            float S2 = 0.f, Q2 = 0.f;
#pragma unroll
            for (int r = 0; r < G; r++) {
                S2 += sv[r * SLICE + tid];
                Q2 += sq[r * SLICE + tid];
            }
            part[((size_t)(yoff + tid) * MAXT + blockIdx.x) * 2] = S2;
            part[((size_t)(yoff + tid) * MAXT + blockIdx.x) * 2 + 1] = Q2;
        }
    }
}

// ---------------------------------------------------------------------------
// First conv, in-CTA K-split: CIN=4, COUT=32, K=125, 128 rows/CTA,
// group0 taps [0,63), group1 [63,125); combine + ReLU + quad store.
// ---------------------------------------------------------------------------
__global__ __launch_bounds__(256, 3) void conv1_m(
    const float* __restrict__ geo, const float* __restrict__ col,
    const float* __restrict__ W, const int* __restrict__ in_map, int n_in,
    int n_out, float4* __restrict__ oT4) {
    extern __shared__ float sm[];  // 125*128 floats
    const int tid = threadIdx.x;
    const int wg = tid >> 7;
    const int wtid = tid & 127;

    for (int i = tid; i < 125 * 32; i += 256)
        reinterpret_cast<float4*>(sm)[i] = reinterpret_cast<const float4*>(W)[i];
    __syncthreads();

    const int row = blockIdx.x * 128 + wtid;
    const bool rowok = row < n_out;
    const int k0 = wg ? 63 : 0;
    const int k1 = wg ? 125 : 63;

    ull acc[16];
#pragma unroll
    for (int i = 0; i < 16; i++) acc[i] = 0ull;

    int idxn = rowok ? __ldg(&in_map[(size_t)k0 * n_out + row]) : n_in;
    for (int k = k0; k < k1; k++) {
        int idx = idxn;
        if (k + 1 < k1)
            idxn = rowok ? __ldg(&in_map[(size_t)(k + 1) * n_out + row]) : n_in;
        if (idx >= n_in) continue;

        float fr[4];
        fr[0] = __ldg(&geo[idx]);
        fr[1] = __ldg(&col[(size_t)idx * 3]);
        fr[2] = __ldg(&col[(size_t)idx * 3 + 1]);
        fr[3] = __ldg(&col[(size_t)idx * 3 + 2]);
        const float* wk = sm + k * 128;
#pragma unroll
        for (int c = 0; c < 4; c++) {
            ull a2 = pack2(fr[c]);
            const ulonglong2* wrow = reinterpret_cast<const ulonglong2*>(wk + c * 32);
#pragma unroll
            for (int p = 0; p < 8; p++) {
                ulonglong2 w = wrow[p];
                fma2(acc[2 * p], a2, w.x);
                fma2(acc[2 * p + 1], a2, w.y);
            }
        }
    }

    float vs[32];
#pragma unroll
    for (int p = 0; p < 16; p++) {
        float2 v = *reinterpret_cast<float2*>(&acc[p]);
        vs[2 * p] = v.x;
        vs[2 * p + 1] = v.y;
    }
    __syncthreads();
    float* cmb = sm;  // 128*32 floats
    if (wg == 1) {
#pragma unroll
        for (int s = 0; s < 32; s++) cmb[wtid * 32 + s] = vs[s];
    }
    __syncthreads();
    if (wg == 0 && rowok) {
#pragma unroll
        for (int p = 0; p < 8; p++) {
            float4 o;
            o.x = fmaxf(vs[4 * p] + cmb[wtid * 32 + 4 * p], 0.f);
            o.y = fmaxf(vs[4 * p + 1] + cmb[wtid * 32 + 4 * p + 1], 0.f);
            o.z = fmaxf(vs[4 * p + 2] + cmb[wtid * 32 + 4 * p + 2], 0.f);
            o.w = fmaxf(vs[4 * p + 3] + cmb[wtid * 32 + 4 * p + 3], 0.f);
            oT4[(size_t)p * n_out + row] = o;
        }
    }
}

// Warp-folded BN params for channel c over ntiles partials.
__device__ __forceinline__ void bn_fold(const float* part, int c, int ntiles,
                                        int n, const float* g, const float* b,
                                        int lane, float* sc_out, float* sh_out) {
    float s = 0.f, q = 0.f;
    for (int i = lane; i < ntiles; i += 32) {
        s += part[((size_t)c * MAXT + i) * 2];
        q += part[((size_t)c * MAXT + i) * 2 + 1];
    }
#pragma unroll
    for (int o = 16; o >= 1; o >>= 1) {
        s += __shfl_down_sync(0xffffffffu, s, o);
        q += __shfl_down_sync(0xffffffffu, q, o);
    }
    if (lane == 0) {
        float inv_n = 1.f / (float)n;
        float mu = s * inv_n;
        float var = q * inv_n - mu * mu;
        float sc = __ldg(&g[c]) * rsqrtf(var + 1e-5f);
        *sc_out = sc;
        *sh_out = __ldg(&b[c]) - mu * sc;
    }
}

// xt = relu(z*sc+sh), quad layout; BN reduce folded.
__global__ __launch_bounds__(256) void apply4(
    const float4* __restrict__ z, const float* __restrict__ part, int ntiles,
    const float* __restrict__ g, const float* __restrict__ bb,
    float4* __restrict__ out, int n) {
    __shared__ float sp[8];
    const int quad = blockIdx.y, tid = threadIdx.x;
    const int w = tid >> 5, lane = tid & 31;
    if (w < 4)
        bn_fold(part, 4 * quad + w, ntiles, n, g, bb, lane, &sp[2 * w], &sp[2 * w + 1]);
    __syncthreads();
    const float sc0 = sp[0], sh0 = sp[1], sc1 = sp[2], sh1 = sp[3];
    const float sc2 = sp[4], sh2 = sp[5], sc3 = sp[6], sh3 = sp[7];
    const size_t base = (size_t)quad * n;
    for (int i = blockIdx.x * 256 + tid; i < n; i += gridDim.x * 256) {
        float4 v = z[base + i];
        float4 o;
        o.x = fmaxf(v.x * sc0 + sh0, 0.f);
        o.y = fmaxf(v.y * sc1 + sh1, 0.f);
        o.z = fmaxf(v.z * sc2 + sh2, 0.f);
        o.w = fmaxf(v.w * sc3 + sh3, 0.f);
        out[base + i] = o;
    }
}

// out = relu(z*sc+sh + res), quad layout; BN reduce folded.
__global__ __launch_bounds__(256) void res4(
    const float4* __restrict__ z, const float* __restrict__ part, int ntiles,
    const float* __restrict__ g, const float* __restrict__ bb,
    const float4* __restrict__ res, float4* __restrict__ out, int n) {
    __shared__ float sp[8];
    const int quad = blockIdx.y, tid = threadIdx.x;
    const int w = tid >> 5, lane = tid & 31;
    if (w < 4)
        bn_fold(part, 4 * quad + w, ntiles, n, g, bb, lane, &sp[2 * w], &sp[2 * w + 1]);
    __syncthreads();
    const float sc0 = sp[0], sh0 = sp[1], sc1 = sp[2], sh1 = sp[3];
    const float sc2 = sp[4], sh2 = sp[5], sc3 = sp[6], sh3 = sp[7];
    const size_t base = (size_t)quad * n;
    for (int i = blockIdx.x * 256 + tid; i < n; i += gridDim.x * 256) {
        float4 v = z[base + i], vr = res[base + i];
        float4 o;
        o.x = fmaxf(v.x * sc0 + sh0 + vr.x, 0.f);
        o.y = fmaxf(v.y * sc1 + sh1 + vr.y, 0.f);
        o.z = fmaxf(v.z * sc2 + sh2 + vr.z, 0.f);
        o.w = fmaxf(v.w * sc3 + sh3 + vr.w, 0.f);
        out[base + i] = o;
    }
}

// Final: relu(z*sc+sh + res) quad-SoA -> AoS d_out; BN reduce folded.
__global__ __launch_bounds__(256) void final4(
    const float* __restrict__ z, const float* __restrict__ part, int ntiles,
    const float* __restrict__ g, const float* __restrict__ bb,
    const float* __restrict__ res, float* __restrict__ out, int n) {
    __shared__ float t[64 * 65];
    __shared__ float spar[64], sshf[64], rs[256], rq[256];
    const int tid = threadIdx.x;
    {
        const int c = tid >> 2, r = tid & 3;
        float S = 0.f, Q = 0.f;
        for (int i = r; i < ntiles; i += 4) {
            S += part[((size_t)c * MAXT + i) * 2];
            Q += part[((size_t)c * MAXT + i) * 2 + 1];
        }
        rs[tid] = S;
        rq[tid] = Q;
    }
    __syncthreads();
    if (tid < 64) {
        float S = rs[4 * tid] + rs[4 * tid + 1] + rs[4 * tid + 2] + rs[4 * tid + 3];
        float Q = rq[4 * tid] + rq[4 * tid + 1] + rq[4 * tid + 2] + rq[4 * tid + 3];
        float inv_n = 1.f / (float)n;
        float mu = S * inv_n;
        float var = Q * inv_n - mu * mu;
        float sc = __ldg(&g[tid]) * rsqrtf(var + 1e-5f);
        spar[tid] = sc;
        sshf[tid] = __ldg(&bb[tid]) - mu * sc;
    }
    __syncthreads();

    const int R0 = blockIdx.x * 64;
    for (int i = tid; i < 4096; i += 256) {
        int c = i >> 6, r = i & 63;
        int row = R0 + r;
        float v = 0.f;
        if (row < n) {
            size_t o = ((size_t)(c >> 2) * n + row) * 4 + (c & 3);
            v = fmaxf(z[o] * spar[c] + sshf[c] + res[o], 0.f);
        }
        t[c * 65 + r] = v;
    }
    __syncthreads();
    for (int i = tid; i < 4096; i += 256) {
        int r = i >> 6, c = i & 63;
        int row = R0 + r;
        if (row < n) out[(size_t)row * 64 + c] = t[c * 65 + r];
    }
}

// ---------------------------------------------------------------------------
extern "C" void kernel_launch(void* const* d_in, const int* in_sizes, int n_in,
                              void* d_out, int out_size) {
    const float* x_geo = (const float*)d_in[0];
    const float* x_col = (const float*)d_in[1];
    const float* w0 = (const float*)d_in[2];
    const float* w_e1 = (const float*)d_in[3];
    const float* g_e1 = (const float*)d_in[4];
    const float* b_e1 = (const float*)d_in[5];
    const float* w2 = (const float*)d_in[6];
    const float* w_e2 = (const float*)d_in[7];
    const float* g_e2 = (const float*)d_in[8];
    const float* b_e2 = (const float*)d_in[9];
    const int* m1_in = (const int*)d_in[10];
    const int* m2_in = (const int*)d_in[12];
    const int* m3_in = (const int*)d_in[14];
    const int* m4_in = (const int*)d_in[16];

    const int N = in_sizes[0];
    const int n2 = in_sizes[10] / 125;
    const int n4 = in_sizes[14] / 27;

    float *xc, *z, *xt, *yb, *part;
    cudaGetSymbolAddress((void**)&xc, g_xc);
    cudaGetSymbolAddress((void**)&z, g_z);
    cudaGetSymbolAddress((void**)&xt, g_xt);
    cudaGetSymbolAddress((void**)&yb, g_y);
    cudaGetSymbolAddress((void**)&part, g_part);

    const int SM1 = 125 * 4 * 32 * 4;         // 64000
    const int SME1 = 27 * 32 * 16 * 4;        // 55296 (CIN32 SLICE16)
    const int SMC2 = 27 * 32 * 8 * 4;         // 27648 (CIN32 SLICE8)
    const int SME2 = 27 * 64 * 8 * 4;         // 55296 (CIN64 SLICE8)
    cudaFuncSetAttribute(conv1_m, cudaFuncAttributeMaxDynamicSharedMemorySize, SM1);
    cudaFuncSetAttribute(conv_m<32, 16, true>, cudaFuncAttributeMaxDynamicSharedMemorySize, SME1);
    cudaFuncSetAttribute(conv_m<32, 8, false>, cudaFuncAttributeMaxDynamicSharedMemorySize, SMC2);
    cudaFuncSetAttribute(conv_m<64, 8, true>, cudaFuncAttributeMaxDynamicSharedMemorySize, SME2);

    const int tiles2 = (n2 + 255) / 256;
    const int tiles4 = (n4 + 255) / 256;
    const dim3 ge1(tiles2, 2);                // COUT32 / SLICE16
    const dim3 gc2(tiles4, 8);                // COUT64 / SLICE8
    const dim3 ge2(tiles4, 8);
    const dim3 ga1((n2 + 2047) / 2048, 8);
    const dim3 ga2((n4 + 2047) / 2048, 16);

    // conv1 (k5 s2, 4->32) + ReLU -> xc (quad SoA), K-split in-CTA
    conv1_m<<<(n2 + 127) / 128, 256, SM1>>>(x_geo, x_col, w0, m1_in, N, n2,
                                            (float4*)xc);

    // enc1: 2 BasicBlocks, 32ch (stats fused into conv epilogue)
    for (int i = 0; i < 2; i++) {
        const float* wA = w_e1 + (size_t)(i * 2 + 0) * 27 * 32 * 32;
        const float* wB = w_e1 + (size_t)(i * 2 + 1) * 27 * 32 * 32;
        conv_m<32, 16, true><<<ge1, 256, SME1>>>(
            (const float4*)xc, wA, m2_in, n2, n2, 32, 14, (float4*)z, part);
        apply4<<<ga1, 256>>>((const float4*)z, part, tiles2,
                             g_e1 + (size_t)(i * 2) * 32,
                             b_e1 + (size_t)(i * 2) * 32, (float4*)xt, n2);
        conv_m<32, 16, true><<<ge1, 256, SME1>>>(
            (const float4*)xt, wB, m2_in, n2, n2, 32, 14, (float4*)z, part);
        res4<<<ga1, 256>>>((const float4*)z, part, tiles2,
                           g_e1 + (size_t)(i * 2 + 1) * 32,
                           b_e1 + (size_t)(i * 2 + 1) * 32, (const float4*)xc,
                           (float4*)xc, n2);
    }

    // conv2 (32 -> 64 onto stride-4 coords) -> yb directly
    conv_m<32, 8, false><<<gc2, 256, SMC2>>>(
        (const float4*)xc, w2, m3_in, n2, n4, 64, 14, (float4*)yb, nullptr);

    // enc2: 2 BasicBlocks, 64ch
    for (int i = 0; i < 2; i++) {
        const float* wA = w_e2 + (size_t)(i * 2 + 0) * 27 * 64 * 64;
        const float* wB = w_e2 + (size_t)(i * 2 + 1) * 27 * 64 * 64;
        conv_m<64, 8, true><<<ge2, 256, SME2>>>(
            (const float4*)yb, wA, m4_in, n4, n4, 64, 14, (float4*)z, part);
        apply4<<<ga2, 256>>>((const float4*)z, part, tiles4,
                             g_e2 + (size_t)(i * 2) * 64,
                             b_e2 + (size_t)(i * 2) * 64, (float4*)xt, n4);
        conv_m<64, 8, true><<<ge2, 256, SME2>>>(
            (const float4*)xt, wB, m4_in, n4, n4, 64, 14, (float4*)z, part);
        if (i == 1) {
            final4<<<(n4 + 63) / 64, 256>>>(z, part, tiles4,
                                            g_e2 + (size_t)(i * 2 + 1) * 64,
                                            b_e2 + (size_t)(i * 2 + 1) * 64, yb,
                                            (float*)d_out, n4);
        } else {
            res4<<<ga2, 256>>>((const float4*)z, part, tiles4,
                               g_e2 + (size_t)(i * 2 + 1) * 64,
                               b_e2 + (size_t)(i * 2 + 1) * 64,
                               (const float4*)yb, (float4*)yb, n4);
        }
    }
}